// round 16
// baseline (speedup 1.0000x reference)
#include <cuda_runtime.h>
#include <cuda_fp16.h>
#include <cstdint>

#define DEV_INLINE __device__ __forceinline__

// ---------------- problem sizes ----------------
static constexpr int kB = 16384;
static constexpr int kD = 1024;
static constexpr int kU = 128;

// ---------------- tiling (R5/R15 champion topology) ----------------
static constexpr int DC    = 32;            // K per chunk
static constexpr int NCH   = kD / DC;       // 32 chunks
static constexpr int PAIRS = 3;             // stream pairs (0,1),(2,3),(4,5)
static constexpr int PAIR_BYTES = 128 * 128;           // 128 rows x 128B
static constexpr int HALF_BUF   = PAIRS * PAIR_BYTES;  // 49152 (A region or W region)
static constexpr int BUF_BYTES  = 2 * HALF_BUF;        // 98304 per buffer
static constexpr int SMEM_TOTAL = 2 * BUF_BYTES;       // 196608 double-buffered

static constexpr int W_HALVES = NCH * PAIRS * 8192;    // 786432 fp16
static constexpr int W_U4_PER_CHUNK = PAIRS * 8192 * 2 / 16;  // 3072 uint4

static constexpr int NTHREADS = 384;  // producers wid 0-3 (lo), consumers wid 4-11 (hi)

// prepacked, SW128-swizzled fp16 weights: [chunk32][pair][128 rows][128B (2 streams)]
__device__ __half g_Wpack[W_HALVES];

// ---------------- PTX helpers ----------------
DEV_INLINE uint32_t smem_u32(const void* p) {
    uint32_t a;
    asm("{ .reg .u64 t; cvta.to.shared.u64 t, %1; cvt.u32.u64 %0, t; }" : "=r"(a) : "l"(p));
    return a;
}

#define LDSM_X4(r, addr)                                                        \
    asm volatile("ldmatrix.sync.aligned.m8n8.x4.shared.b16 {%0,%1,%2,%3}, [%4];"\
                 : "=r"((r)[0]), "=r"((r)[1]), "=r"((r)[2]), "=r"((r)[3])       \
                 : "r"(addr))

DEV_INLINE void mma16816(float* d, const uint32_t* a, uint32_t b0, uint32_t b1) {
    asm volatile(
        "mma.sync.aligned.m16n8k16.row.col.f32.f16.f16.f32 "
        "{%0,%1,%2,%3}, {%4,%5,%6,%7}, {%8,%9}, {%0,%1,%2,%3};"
        : "+f"(d[0]), "+f"(d[1]), "+f"(d[2]), "+f"(d[3])
        : "r"(a[0]), "r"(a[1]), "r"(a[2]), "r"(a[3]), "r"(b0), "r"(b1));
}

DEV_INLINE void cp_async16(uint32_t smem_dst, const void* gsrc) {
    asm volatile("cp.async.cg.shared.global [%0], [%1], 16;"
                 :: "r"(smem_dst), "l"(gsrc) : "memory");
}
DEV_INLINE void cp_async_commit() { asm volatile("cp.async.commit_group;" ::: "memory"); }
DEV_INLINE void cp_async_wait_all() { asm volatile("cp.async.wait_group 0;" ::: "memory"); }

// ---------------- weight prep: vectorized (one uint4 store per thread) ----------------
__global__ void kan_prep_weights(const float* __restrict__ bw,
                                 const float* __restrict__ sw) {
    int u = blockIdx.x * blockDim.x + threadIdx.x;   // 0..98303
    if (u >= W_HALVES / 8) return;
    int g16 = u & 7;               // 16B group within the 128B row
    int n   = (u >> 3) & 127;      // output unit
    int t3  = u >> 10;             // c*3 + p
    int p   = t3 % 3;
    int c   = t3 / 3;
    int slo = g16 >> 2;            // stream half (0/1)
    int k0  = (g16 & 3) * 8;       // first k of this group
    int s   = p * 2 + slo;         // stream 0..5 (0 = base weights)

    __half h[8];
    #pragma unroll
    for (int j = 0; j < 8; ++j) {
        int i = c * DC + k0 + j;
        float v = (s == 0) ? bw[i * kU + n]
                           : sw[(size_t)(i * kU + n) * 8 + (s - 1)];
        h[j] = __float2half(v);
    }
    unsigned off = (unsigned)(n * 128 + slo * 64 + k0 * 2);   // 16B aligned
    unsigned swz = off ^ ((off >> 3) & 0x70);
    *reinterpret_cast<uint4*>(reinterpret_cast<char*>(g_Wpack) +
                              (size_t)t3 * 16384 + swz) =
        *reinterpret_cast<const uint4*>(h);
}

// ---------------- main fused kernel (consumers on hi-wid) ----------------
__global__ void __launch_bounds__(NTHREADS, 1)
kan_main_kernel(const float* __restrict__ x, float* __restrict__ out) {
    extern __shared__ char smem[];
    const uint32_t smem_base = smem_u32(smem);
    const int tid  = threadIdx.x;
    const int wid  = tid >> 5;
    const int lane = tid & 31;
    const int row_base = blockIdx.x * 128;

    // rbf chain constants
    const float E375p = 42.52108200006278f;    // e^{3.75}
    const float E125p = 3.4903429574597902f;   // e^{1.25}
    const float E125m = 0.2865047968601901f;   // e^{-1.25}
    const float E375m = 0.023517745856009107f; // e^{-3.75}

    if (wid < 4) {
        // ======= PRODUCER warps (wid 0-3, lo-priority; 128 threads, 1 row each) =======
        const int pr = tid;                        // 0..127
        const float* xp = x + (size_t)(row_base + pr) * kD;
        const uint32_t aSw = (uint32_t)((pr & 7) << 4);

        float4 xq[8];                              // one chunk of x, prefetched
        auto loadX = [&](int c) {
            const float* xc = xp + c * DC;
            #pragma unroll
            for (int j = 0; j < 8; ++j)
                xq[j] = *reinterpret_cast<const float4*>(xc + j * 4);
        };

        auto produce = [&](uint32_t aRegionOff) {  // consumes current xq
            #pragma unroll
            for (int g = 0; g < 4; ++g) {
                float xs[8];
                xs[0]=xq[2*g].x;   xs[1]=xq[2*g].y;   xs[2]=xq[2*g].z;   xs[3]=xq[2*g].w;
                xs[4]=xq[2*g+1].x; xs[5]=xq[2*g+1].y; xs[6]=xq[2*g+1].z; xs[7]=xq[2*g+1].w;
                union { __half2 h2[4]; uint4 u4; } st[6];
                #pragma unroll
                for (int e = 0; e < 8; e += 2) {
                    float a0 = xs[e] + 1.f, a1 = xs[e+1] + 1.f;
                    float y0a = __expf(-5.f * a0 * a0);
                    float y0b = __expf(-5.f * a1 * a1);
                    float ta  = __expf(5.f * xs[e]);
                    float tb  = __expf(5.f * xs[e+1]);
                    float y1a = y0a * ta * E375p, y1b = y0b * tb * E375p;
                    float y2a = y1a * ta * E125p, y2b = y1b * tb * E125p;
                    float y3a = y2a * ta * E125m, y3b = y2b * tb * E125m;
                    float y4a = y3a * ta * E375m, y4b = y3b * tb * E375m;
                    int j = e >> 1;
                    st[0].h2[j] = __floats2half2_rn(xs[e], xs[e+1]);
                    st[1].h2[j] = __floats2half2_rn(y0a, y0b);
                    st[2].h2[j] = __floats2half2_rn(y1a, y1b);
                    st[3].h2[j] = __floats2half2_rn(y2a, y2b);
                    st[4].h2[j] = __floats2half2_rn(y3a, y3b);
                    st[5].h2[j] = __floats2half2_rn(y4a, y4b);
                }
                #pragma unroll
                for (int s = 0; s < 6; ++s) {
                    int p = s >> 1, slo = s & 1;
                    unsigned off = (unsigned)(pr * 128 + slo * 64 + g * 16);
                    unsigned swz = off ^ aSw;
                    *reinterpret_cast<uint4*>(smem + aRegionOff + p * PAIR_BYTES + swz)
                        = st[s].u4;
                }
            }
        };

        auto copyW = [&](int c, uint32_t wRegion) {
            const char* src = reinterpret_cast<const char*>(g_Wpack) +
                              (size_t)c * (PAIRS * 8192 * 2);
            #pragma unroll
            for (int j = 0; j < W_U4_PER_CHUNK / 128; ++j) {  // 24 per thread
                int i = pr + j * 128;
                cp_async16(wRegion + i * 16, src + i * 16);
            }
            cp_async_commit();
        };

        // prologue: chunk 0 -> buffer 0 (and prefetch x(1))
        loadX(0);
        copyW(0, smem_base + HALF_BUF);
        produce(0);
        if (NCH > 1) loadX(1);
        cp_async_wait_all();
        __syncthreads();

        for (int c = 0; c < NCH; ++c) {
            if (c + 1 < NCH) {
                const uint32_t bufOff = (uint32_t)(((c + 1) & 1) * BUF_BYTES);
                copyW(c + 1, smem_base + bufOff + HALF_BUF);
                produce(bufOff);                  // x(c+1) already in registers
                if (c + 2 < NCH) loadX(c + 2);    // prefetch next
                cp_async_wait_all();
            }
            __syncthreads();
        }
    } else {
        // ======= CONSUMER warps (wid 4-11, HI-priority): 64x32 tiles =======
        const int w  = wid - 4;        // 0..7
        const int mi = w & 1;          // rows mi*64
        const int ni = w >> 1;         // cols ni*32

        float acc0[4][4][4], acc1[4][4][4];
        #pragma unroll
        for (int a = 0; a < 4; ++a)
            #pragma unroll
            for (int b = 0; b < 4; ++b)
                #pragma unroll
                for (int j = 0; j < 4; ++j) { acc0[a][b][j] = 0.f; acc1[a][b][j] = 0.f; }

        const int aRowLocal  = (lane & 7) + ((lane >> 3) & 1) * 8;
        const uint32_t kbAhi = ((lane >> 4) & 1) * 16;
        uint32_t aOff[4], aXor[4];
        #pragma unroll
        for (int mb = 0; mb < 4; ++mb) {
            int r = mi * 64 + mb * 16 + aRowLocal;
            aOff[mb] = (uint32_t)(r * 128);
            aXor[mb] = (uint32_t)((r & 7) << 4);
        }
        const int rB = ni * 32 + lane;
        const uint32_t bOff = (uint32_t)(rB * 128);
        const uint32_t bXor = (uint32_t)((rB & 7) << 4);

        __syncthreads();  // matches producer prologue sync

        for (int c = 0; c < NCH; ++c) {
            const uint32_t bufc  = smem_base + (uint32_t)((c & 1) * BUF_BYTES);
            const uint32_t aBase = bufc;
            const uint32_t bBase = bufc + HALF_BUF;

            #pragma unroll
            for (int kk = 0; kk < 2; ++kk) {
                #pragma unroll
                for (int s = 0; s < 6; ++s) {
                    const int p = s >> 1, slo = s & 1;
                    const uint32_t pOff = (uint32_t)(p * PAIR_BYTES);
                    const uint32_t kbC  = (uint32_t)(slo * 64 + kk * 32);

                    // B first: the MMAs' earliest dependency
                    uint32_t bb[8];
                    LDSM_X4(bb,     bBase + pOff + bOff + ((kbC + 0u)  ^ bXor));
                    LDSM_X4(bb + 4, bBase + pOff + bOff + ((kbC + 16u) ^ bXor));

                    uint32_t a[16];
                    {
                        const uint32_t kbA = kbC + kbAhi;
                        #pragma unroll
                        for (int mb = 0; mb < 4; ++mb)
                            LDSM_X4(a + mb * 4,
                                    aBase + pOff + aOff[mb] + (kbA ^ aXor[mb]));
                    }

                    if (s == 0) {
                        #pragma unroll
                        for (int mb = 0; mb < 4; ++mb)
                            #pragma unroll
                            for (int nb = 0; nb < 4; ++nb)
                                mma16816(acc0[mb][nb], a + mb * 4, bb[nb], bb[4 + nb]);
                    } else {
                        #pragma unroll
                        for (int mb = 0; mb < 4; ++mb)
                            #pragma unroll
                            for (int nb = 0; nb < 4; ++nb)
                                mma16816(acc1[mb][nb], a + mb * 4, bb[nb], bb[4 + nb]);
                    }
                }
            }
            __syncthreads();
        }

        // epilogue: SiLU(base) + spline
        const int colBase = ni * 32 + (lane & 3) * 2;
        #pragma unroll
        for (int mb = 0; mb < 4; ++mb) {
            int row0 = row_base + mi * 64 + mb * 16 + (lane >> 2);
            #pragma unroll
            for (int nb = 0; nb < 4; ++nb) {
                int col = colBase + nb * 8;
                float z0 = acc0[mb][nb][0], z1 = acc0[mb][nb][1];
                float z2 = acc0[mb][nb][2], z3 = acc0[mb][nb][3];
                float2 v0, v1;
                v0.x = __fdividef(z0, 1.f + __expf(-z0)) + acc1[mb][nb][0];
                v0.y = __fdividef(z1, 1.f + __expf(-z1)) + acc1[mb][nb][1];
                v1.x = __fdividef(z2, 1.f + __expf(-z2)) + acc1[mb][nb][2];
                v1.y = __fdividef(z3, 1.f + __expf(-z3)) + acc1[mb][nb][3];
                *reinterpret_cast<float2*>(out + (size_t)row0 * kU + col)       = v0;
                *reinterpret_cast<float2*>(out + (size_t)(row0 + 8) * kU + col) = v1;
            }
        }
    }
}

// ---------------- launch ----------------
extern "C" void kernel_launch(void* const* d_in, const int* in_sizes, int n_in,
                              void* d_out, int out_size) {
    (void)in_sizes; (void)n_in; (void)out_size;
    const float* x  = (const float*)d_in[0];
    const float* bw = (const float*)d_in[1];
    const float* sw = (const float*)d_in[2];
    float* out = (float*)d_out;

    cudaFuncSetAttribute(kan_main_kernel,
                         cudaFuncAttributeMaxDynamicSharedMemorySize, SMEM_TOTAL);

    kan_prep_weights<<<(W_HALVES / 8 + 255) / 256, 256>>>(bw, sw);
    kan_main_kernel<<<kB / 128, NTHREADS, SMEM_TOTAL>>>(x, out);
}